// round 7
// baseline (speedup 1.0000x reference)
#include <cuda_runtime.h>
#include <math.h>

// Problem shape (fixed for this dataset entry)
#define BATCH 1024
#define SEQL  512
#define NTAG  64
#define WARPS_PER_CTA 8
#define CTA_THREADS (WARPS_PER_CTA * 32)

// CRF forward NLL, linear-domain scan with power-of-two renormalization:
//   u_t[j] = exp(alpha_t[j] - M_t),  M_t = Esum_t * ln2  (Esum integer, exact)
//   v_j = (sum_i u_i * E[i][j]) * exp(em_j + cmax_j)
//   e = exponent(v_0);  u_next = v * 2^-e;  Esum += e
//   logZ = Esum*ln2 + log(sum_j u_final[j])
// E[i][j] = exp(trans[i][j] - cmax[j]) lives in REGISTERS as f32x2 pairs;
// matvec uses packed fma.rn.f32x2 (64 FFMA2/step/lane).
// This removes the per-step 5-shuffle max-reduce and both __logf calls
// from the critical path (kernel was latency-bound: issue 41%, fma 24%).

__device__ __forceinline__ unsigned long long pack_f32x2(float lo, float hi) {
    return ((unsigned long long)__float_as_uint(hi) << 32) | __float_as_uint(lo);
}
__device__ __forceinline__ float lo_f32(unsigned long long v) {
    return __uint_as_float((unsigned)(v & 0xffffffffull));
}
__device__ __forceinline__ float hi_f32(unsigned long long v) {
    return __uint_as_float((unsigned)(v >> 32));
}
__device__ __forceinline__ unsigned long long fma_f32x2(unsigned long long a,
                                                        unsigned long long b,
                                                        unsigned long long c) {
    unsigned long long d;
    asm("fma.rn.f32x2 %0, %1, %2, %3;" : "=l"(d) : "l"(a), "l"(b), "l"(c));
    return d;
}
__device__ __forceinline__ unsigned long long add_f32x2(unsigned long long a,
                                                        unsigned long long b) {
    unsigned long long d;
    asm("add.rn.f32x2 %0, %1, %2;" : "=l"(d) : "l"(a), "l"(b));
    return d;
}

__global__ __launch_bounds__(CTA_THREADS, 1)
void crf_fwd_kernel(const float* __restrict__ logits,
                    const int*   __restrict__ tags32,   // raw tag words (int32 view)
                    const int*   __restrict__ mask,
                    const float* __restrict__ trans,
                    float* __restrict__ out)
{
    __shared__ float  trans_s[NTAG * NTAG];   // raw transitions (16 KB) — gold lookups
    __shared__ float  cmax_s[NTAG];
    // u double-buffer, entries pre-duplicated: pb[w][buf][i] = {u_i, u_i}
    __shared__ __align__(16) float2 pb[WARPS_PER_CTA][2][NTAG];   // 8 KB
    __shared__ int tags_is64_s;

    const int tid  = threadIdx.x;
    const int warp = tid >> 5;
    const int lane = tid & 31;

    // ---- per-CTA init ----
    for (int k = tid; k < NTAG * NTAG; k += CTA_THREADS)
        trans_s[k] = trans[k];
    if (tid == 0) {
        int odd_or = 0;
        #pragma unroll
        for (int w = 1; w < 64; w += 2)
            odd_or |= tags32[w];
        tags_is64_s = (odd_or == 0) ? 1 : 0;   // int64 tags: odd words all zero
    }
    __syncthreads();

    if (tid < NTAG) {
        float m = -3.402823466e38f;
        #pragma unroll
        for (int i = 0; i < NTAG; i++)
            m = fmaxf(m, trans_s[i * NTAG + tid]);
        cmax_s[tid] = m;
    }
    __syncthreads();

    const bool is64 = (tags_is64_s != 0);
    const int  j0   = 2 * lane;
    const float2 cm = make_float2(cmax_s[j0], cmax_s[j0 + 1]);

    // ---- E into registers: E_r[i] = { exp(trans[i][j0]-cm.x), exp(trans[i][j0+1]-cm.y) }
    unsigned long long E_r[NTAG];
    #pragma unroll
    for (int i = 0; i < NTAG; i++) {
        const float ex = __expf(trans_s[i * NTAG + j0]     - cm.x);
        const float ey = __expf(trans_s[i * NTAG + j0 + 1] - cm.y);
        E_r[i] = pack_f32x2(ex, ey);
    }

    // ---- one warp per batch chain ----
    const int b = blockIdx.x * WARPS_PER_CTA + warp;

    const float* emit_base = logits + (size_t)b * SEQL * NTAG;
    const int*   mask_base = mask   + (size_t)b * SEQL;
    const size_t tbase     = (size_t)b * SEQL;

    auto load_tag = [&](int t) -> int {
        return is64 ? tags32[2 * (tbase + t)] : tags32[tbase + t];
    };

    // t = 0: u init + gold emission
    const float2 em0 = *reinterpret_cast<const float2*>(emit_base + j0);
    float ux = __expf(em0.x);
    float uy = __expf(em0.y);
    *reinterpret_cast<float4*>(&pb[warp][0][j0]) = make_float4(ux, ux, uy, uy);

    int   tg_prev = load_tag(0);
    float mk0     = (float)mask_base[0];
    float gold = 0.0f;
    if (tg_prev == j0)          gold = em0.x * mk0;
    else if (tg_prev == j0 + 1) gold = em0.y * mk0;

    int Esum = 0;

    // prefetch pipeline, depth 2 (em is the DRAM-latency-critical stream)
    float2 emc = *reinterpret_cast<const float2*>(emit_base + NTAG + j0); // t=1
    int    tgc = load_tag(1);
    float  mkc = (float)mask_base[1];
    float2 emn = *reinterpret_cast<const float2*>(emit_base + 2 * NTAG + j0); // t=2
    int    tgn = load_tag(2);
    float  mkn = (float)mask_base[2];

    __syncwarp();

    int buf = 0;
    for (int t = 1; t < SEQL; t++) {
        // prefetch t+2
        float2 em_p = make_float2(0.f, 0.f);
        int    tg_p = 0;
        float  mk_p = 0.f;
        if (t + 2 < SEQL) {
            em_p = *reinterpret_cast<const float2*>(emit_base + (size_t)(t + 2) * NTAG + j0);
            tg_p = load_tag(t + 2);
            mk_p = (float)mask_base[t + 2];
        }

        // hoist exp(em + cmax): independent of the matvec below
        const float ex = __expf(emc.x + cm.x);
        const float ey = __expf(emc.y + cm.y);

        // matvec: s[j0], s[j0+1] = sum_i u_i * E[i][j]  (packed f32x2, 4 chains)
        const float4* pbp = reinterpret_cast<const float4*>(&pb[warp][buf][0]);
        unsigned long long acc0 = 0ull, acc1 = 0ull, acc2 = 0ull, acc3 = 0ull;
        #pragma unroll
        for (int k = 0; k < NTAG / 4; k++) {            // 16 iterations, i = 4k..4k+3
            const float4 q0 = pbp[2 * k];               // {u_i,u_i,u_{i+1},u_{i+1}}
            const float4 q1 = pbp[2 * k + 1];
            const unsigned long long pA = pack_f32x2(q0.x, q0.y);
            const unsigned long long pB = pack_f32x2(q0.z, q0.w);
            const unsigned long long pC = pack_f32x2(q1.x, q1.y);
            const unsigned long long pD = pack_f32x2(q1.z, q1.w);
            acc0 = fma_f32x2(pA, E_r[4 * k],     acc0);
            acc1 = fma_f32x2(pB, E_r[4 * k + 1], acc1);
            acc2 = fma_f32x2(pC, E_r[4 * k + 2], acc2);
            acc3 = fma_f32x2(pD, E_r[4 * k + 3], acc3);
        }
        const unsigned long long sp =
            add_f32x2(add_f32x2(acc0, acc1), add_f32x2(acc2, acc3));

        const float vx = lo_f32(sp) * ex;
        const float vy = hi_f32(sp) * ey;

        // power-of-two renormalizer from lane 0's value (exact, no MUFU)
        const float r = __shfl_sync(0xffffffffu, vx, 0);
        const int   e = (int)((__float_as_uint(r) >> 23) & 255u) - 127;
        const float q = __uint_as_float((unsigned)(127 - e) << 23);  // 2^-e exactly

        if (mkc > 0.f) {
            ux = vx * q;
            uy = vy * q;
            Esum += e;
        }
        *reinterpret_cast<float4*>(&pb[warp][buf ^ 1][j0]) =
            make_float4(ux, ux, uy, uy);

        // gold score contributions for step t
        if (tgc == j0)          gold += emc.x * mkc;
        else if (tgc == j0 + 1) gold += emc.y * mkc;
        if (lane == 0)
            gold += trans_s[tg_prev * NTAG + tgc] * mkc;
        tg_prev = tgc;

        // rotate pipeline
        emc = emn; tgc = tgn; mkc = mkn;
        emn = em_p; tgn = tg_p; mkn = mk_p;
        buf ^= 1;
        __syncwarp();
    }

    // logZ = Esum*ln2 + log(sum_j u[j])
    float s = ux + uy;
    #pragma unroll
    for (int o = 16; o > 0; o >>= 1)
        s += __shfl_xor_sync(0xffffffffu, s, o);

    // reduce gold across warp
    #pragma unroll
    for (int o = 16; o > 0; o >>= 1)
        gold += __shfl_xor_sync(0xffffffffu, gold, o);

    if (lane == 0) {
        const double logZ = (double)Esum * 0.6931471805599453
                          + (double)__logf(s);
        out[b] = (float)(logZ - (double)gold);
    }
}

extern "C" void kernel_launch(void* const* d_in, const int* in_sizes, int n_in,
                              void* d_out, int out_size)
{
    const float* logits = (const float*)d_in[0];
    const int*   tags32 = (const int*)d_in[1];   // dtype detected in-kernel
    const int*   mask   = (const int*)d_in[2];
    const float* trans  = (const float*)d_in[3];
    float*       out    = (float*)d_out;

    const int grid = BATCH / WARPS_PER_CTA; // 128 CTAs, 8 warps (batches) each
    crf_fwd_kernel<<<grid, CTA_THREADS>>>(logits, tags32, mask, trans, out);
}